// round 3
// baseline (speedup 1.0000x reference)
#include <cuda_runtime.h>
#include <cuda_bf16.h>
#include <cuda_fp16.h>
#include <math.h>

#define NN 100000
#define EE 1000000
#define INF 128
#define HH 64
#define BN_EPS 1e-5f

typedef unsigned long long ull;

// ---------------- scratch (device globals, no runtime alloc) ----------------
__device__ int   g_indeg[NN];
__device__ int   g_off[NN + 1];
__device__ int   g_cursor[NN];
__device__ int   g_csr[EE];
__device__ float g_dinv[NN];
__device__ int   g_bsum[128];
__device__ int   g_boff[128];
__device__ int   g_ticket;
__device__ float g_sum[2][HH];
__device__ float g_sq[2][HH];
__device__ float g_scale[2][HH];
__device__ float g_shift[2][HH];

__device__ __half2 g_h[(size_t)NN * 32];   // GEMM output, fp16, pre-scaled by dinv[row]
__device__ float   g_agg[(size_t)NN * HH]; // aggregation output (pre-BN, fp32)

// packed f32x2 FMA (Blackwell dual-fp32 pipe; ptxas never emits this from C++)
__device__ __forceinline__ ull fma2(ull a, ull b, ull c) {
    ull d;
    asm("fma.rn.f32x2 %0, %1, %2, %3;" : "=l"(d) : "l"(a), "l"(b), "l"(c));
    return d;
}

union U64 { ull u; float2 f; };

// ---------------- graph build ----------------

__global__ void zero_kernel() {
    int i = blockIdx.x * blockDim.x + threadIdx.x;
    if (i < NN) g_indeg[i] = 0;
    if (i == 0) g_ticket = 0;
    if (i < HH) {
        g_sum[0][i] = 0.f; g_sum[1][i] = 0.f;
        g_sq[0][i]  = 0.f; g_sq[1][i]  = 0.f;
    }
}

__global__ void hist_kernel(const int* __restrict__ dst) {
    int e = blockIdx.x * blockDim.x + threadIdx.x;
    if (e < EE) atomicAdd(&g_indeg[dst[e]], 1);
}

// per-block sums + (last block) scan of the 98 block sums, fused
__global__ void degscan_kernel(int nb) {
    __shared__ int sh[1024];
    __shared__ int isLast;
    int t = threadIdx.x;
    int idx = blockIdx.x * 1024 + t;
    int v = (idx < NN) ? g_indeg[idx] : 0;
    sh[t] = v;
    __syncthreads();
    for (int s = 512; s > 0; s >>= 1) {
        if (t < s) sh[t] += sh[t + s];
        __syncthreads();
    }
    if (t == 0) {
        g_bsum[blockIdx.x] = sh[0];
        __threadfence();
        isLast = (atomicAdd(&g_ticket, 1) == gridDim.x - 1);
    }
    __syncthreads();
    if (isLast && t < 128) {
        __shared__ int sc[128];
        int bv = (t < nb) ? g_bsum[t] : 0;
        sc[t] = bv;
        __syncthreads();
        for (int o = 1; o < 128; o <<= 1) {
            int a = (t >= o) ? sc[t - o] : 0;
            __syncthreads();
            sc[t] += a;
            __syncthreads();
        }
        if (t < nb) g_boff[t] = sc[t] - bv;   // exclusive
        if (t == nb - 1) g_off[NN] = sc[t];   // == EE
    }
}

__global__ void scan_final_kernel() {
    __shared__ int sh[1024];
    int t = threadIdx.x;
    int idx = blockIdx.x * 1024 + t;
    int v = (idx < NN) ? g_indeg[idx] : 0;
    sh[t] = v;
    __syncthreads();
    for (int o = 1; o < 1024; o <<= 1) {
        int a = (t >= o) ? sh[t - o] : 0;
        __syncthreads();
        sh[t] += a;
        __syncthreads();
    }
    int excl = sh[t] - v;
    if (idx < NN) {
        int off = g_boff[blockIdx.x] + excl;
        g_off[idx] = off;
        g_cursor[idx] = off;
        g_dinv[idx] = rsqrtf((float)(v + 1));  // deg = indeg + self-loop
    }
}

__global__ void fill_kernel(const int* __restrict__ src, const int* __restrict__ dst) {
    int e = blockIdx.x * blockDim.x + threadIdx.x;
    if (e < EE) {
        int d = dst[e];
        int p = atomicAdd(&g_cursor[d], 1);
        g_csr[p] = src[e];
    }
}

// ---------------- GEMM: h[row] = fp16( dinv[row] * (bn_relu?(A[row]) @ W) ) ----------------
// 128x64 tile, 256 threads, 8x4 per thread, f32x2 packed FMA (M-paired accumulators).
template <int K, int DO_BN>
__global__ void gemm_kernel(const float* __restrict__ A, const float* __restrict__ W,
                            __half2* __restrict__ C, int layer) {
    const int KC = 32;
    __shared__ float  Xs[KC][130];   // transposed [k][row]; pad 130: 8B-aligned rows, conflict-light
    __shared__ float2 Ws2[KC][66];   // splatted (w,w); pad 66 keeps rows 16B-aligned
    __shared__ float  s_scale[64], s_shift[64];
    int t = threadIdx.x;
    if (DO_BN) {
        if (t < 64) { s_scale[t] = g_scale[layer][t]; s_shift[t] = g_shift[layer][t]; }
        __syncthreads();
    }
    int tx = t & 15, ty = t >> 4;
    int m0 = blockIdx.x * 128;
    ull acc[4][4];
#pragma unroll
    for (int p = 0; p < 4; p++)
#pragma unroll
        for (int j = 0; j < 4; j++) acc[p][j] = 0ull;

    for (int kc = 0; kc < K; kc += KC) {
        // X tile: 128 rows x 32 k, loaded as float4 along K, stored transposed
#pragma unroll
        for (int l = 0; l < 4; l++) {
            int slot = t + l * 256;       // 0..1023
            int r = slot >> 3;            // 0..127
            int q = slot & 7;             // 0..7  (k-group of 4)
            int row = m0 + r;
            float4 v = make_float4(0.f, 0.f, 0.f, 0.f);
            if (row < NN)
                v = *reinterpret_cast<const float4*>(A + (size_t)row * K + kc + q * 4);
            if (DO_BN) {
                int c = kc + q * 4;
                v.x = fmaxf(fmaf(v.x, s_scale[c + 0], s_shift[c + 0]), 0.f);
                v.y = fmaxf(fmaf(v.y, s_scale[c + 1], s_shift[c + 1]), 0.f);
                v.z = fmaxf(fmaf(v.z, s_scale[c + 2], s_shift[c + 2]), 0.f);
                v.w = fmaxf(fmaf(v.w, s_scale[c + 3], s_shift[c + 3]), 0.f);
            }
            Xs[q * 4 + 0][r] = v.x; Xs[q * 4 + 1][r] = v.y;
            Xs[q * 4 + 2][r] = v.z; Xs[q * 4 + 3][r] = v.w;
        }
        // W tile: 32 k x 64 cols, stored splatted
#pragma unroll
        for (int l = 0; l < 2; l++) {
            int slot = t + l * 256;       // 0..511
            int rw = slot >> 4;           // 0..31
            int c4 = slot & 15;           // 0..15
            float4 v = *reinterpret_cast<const float4*>(W + (size_t)(kc + rw) * 64 + c4 * 4);
            Ws2[rw][c4 * 4 + 0] = make_float2(v.x, v.x);
            Ws2[rw][c4 * 4 + 1] = make_float2(v.y, v.y);
            Ws2[rw][c4 * 4 + 2] = make_float2(v.z, v.z);
            Ws2[rw][c4 * 4 + 3] = make_float2(v.w, v.w);
        }
        __syncthreads();
#pragma unroll
        for (int k = 0; k < KC; k++) {
            const ulonglong2* bp = reinterpret_cast<const ulonglong2*>(&Ws2[k][tx * 4]);
            ulonglong2 b01 = bp[0];
            ulonglong2 b23 = bp[1];
            ull a2[4];
#pragma unroll
            for (int p = 0; p < 4; p++)
                a2[p] = *reinterpret_cast<const ull*>(&Xs[k][ty * 8 + 2 * p]);
#pragma unroll
            for (int p = 0; p < 4; p++) {
                acc[p][0] = fma2(a2[p], b01.x, acc[p][0]);
                acc[p][1] = fma2(a2[p], b01.y, acc[p][1]);
                acc[p][2] = fma2(a2[p], b23.x, acc[p][2]);
                acc[p][3] = fma2(a2[p], b23.y, acc[p][3]);
            }
        }
        __syncthreads();
    }
    // epilogue: unpack pairs (rows 2p, 2p+1), scale by dinv, convert to fp16
#pragma unroll
    for (int p = 0; p < 4; p++) {
        int r0 = m0 + ty * 8 + 2 * p;
        int r1 = r0 + 1;
        U64 u0, u1, u2, u3;
        u0.u = acc[p][0]; u1.u = acc[p][1]; u2.u = acc[p][2]; u3.u = acc[p][3];
        if (r0 < NN) {
            float di = g_dinv[r0];
            __half2 h01 = __floats2half2_rn(u0.f.x * di, u1.f.x * di);
            __half2 h23 = __floats2half2_rn(u2.f.x * di, u3.f.x * di);
            uint2 pk;
            pk.x = *reinterpret_cast<unsigned int*>(&h01);
            pk.y = *reinterpret_cast<unsigned int*>(&h23);
            *reinterpret_cast<uint2*>(&C[(size_t)r0 * 32 + tx * 2]) = pk;
        }
        if (r1 < NN) {
            float di = g_dinv[r1];
            __half2 h01 = __floats2half2_rn(u0.f.y * di, u1.f.y * di);
            __half2 h23 = __floats2half2_rn(u2.f.y * di, u3.f.y * di);
            uint2 pk;
            pk.x = *reinterpret_cast<unsigned int*>(&h01);
            pk.y = *reinterpret_cast<unsigned int*>(&h23);
            *reinterpret_cast<uint2*>(&C[(size_t)r1 * 32 + tx * 2]) = pk;
        }
    }
}

// ---------------- aggregation (fp16 gather) + fused BN statistics ----------------
__global__ void aggstats_kernel(const __half2* __restrict__ h, const float* __restrict__ bias,
                                float* __restrict__ out, int layer) {
    __shared__ float s_sum[64], s_sq[64];
    int t = threadIdx.x;
    if (t < 64) { s_sum[t] = 0.f; s_sq[t] = 0.f; }
    __syncthreads();
    int lane = t & 31;
    int warpId = blockIdx.x * (blockDim.x >> 5) + (t >> 5);
    int totalWarps = gridDim.x * (blockDim.x >> 5);
    float2 b = reinterpret_cast<const float2*>(bias)[lane];
    float sx = 0.f, sy = 0.f, sxx = 0.f, syy = 0.f;

    for (int i = warpId; i < NN; i += totalWarps) {
        float di = g_dinv[i];
        float2 acc = __half22float2(h[(size_t)i * 32 + lane]);  // self-loop (pre-scaled)
        int e0 = g_off[i], e1 = g_off[i + 1];
        int j = e0;
        for (; j + 3 < e1; j += 4) {
            int s0 = g_csr[j], s1 = g_csr[j + 1], s2 = g_csr[j + 2], s3 = g_csr[j + 3];
            float2 v0 = __half22float2(h[(size_t)s0 * 32 + lane]);
            float2 v1 = __half22float2(h[(size_t)s1 * 32 + lane]);
            float2 v2 = __half22float2(h[(size_t)s2 * 32 + lane]);
            float2 v3 = __half22float2(h[(size_t)s3 * 32 + lane]);
            acc.x += (v0.x + v1.x) + (v2.x + v3.x);
            acc.y += (v0.y + v1.y) + (v2.y + v3.y);
        }
        for (; j < e1; j++) {
            float2 v = __half22float2(h[(size_t)g_csr[j] * 32 + lane]);
            acc.x += v.x; acc.y += v.y;
        }
        float ox = fmaf(acc.x, di, b.x);
        float oy = fmaf(acc.y, di, b.y);
        reinterpret_cast<float2*>(out)[(size_t)i * 32 + lane] = make_float2(ox, oy);
        sx += ox; sxx += ox * ox;
        sy += oy; syy += oy * oy;
    }
    atomicAdd(&s_sum[lane * 2 + 0], sx);
    atomicAdd(&s_sq [lane * 2 + 0], sxx);
    atomicAdd(&s_sum[lane * 2 + 1], sy);
    atomicAdd(&s_sq [lane * 2 + 1], syy);
    __syncthreads();
    if (t < 64) {
        atomicAdd(&g_sum[layer][t], s_sum[t]);
        atomicAdd(&g_sq[layer][t], s_sq[t]);
    }
}

__global__ void bnprep_kernel(int layer, const float* __restrict__ gamma,
                              const float* __restrict__ beta) {
    int c = threadIdx.x;
    if (c < HH) {
        float m   = g_sum[layer][c] * (1.0f / NN);
        float var = g_sq[layer][c] * (1.0f / NN) - m * m;
        float sc  = gamma[c] * rsqrtf(var + BN_EPS);
        g_scale[layer][c] = sc;
        g_shift[layer][c] = beta[c] - m * sc;
    }
}

__global__ void bnapply_kernel(const float* __restrict__ v, int layer,
                               float* __restrict__ out) {
    int idx = blockIdx.x * blockDim.x + threadIdx.x;  // over NN*16 float4
    if (idx >= NN * 16) return;
    float4 x = reinterpret_cast<const float4*>(v)[idx];
    int c = (idx & 15) * 4;
    x.x = fmaxf(fmaf(x.x, g_scale[layer][c + 0], g_shift[layer][c + 0]), 0.f);
    x.y = fmaxf(fmaf(x.y, g_scale[layer][c + 1], g_shift[layer][c + 1]), 0.f);
    x.z = fmaxf(fmaf(x.z, g_scale[layer][c + 2], g_shift[layer][c + 2]), 0.f);
    x.w = fmaxf(fmaf(x.w, g_scale[layer][c + 3], g_shift[layer][c + 3]), 0.f);
    reinterpret_cast<float4*>(out)[idx] = x;
}

// ---------------- launch ----------------
extern "C" void kernel_launch(void* const* d_in, const int* in_sizes, int n_in,
                              void* d_out, int out_size) {
    const float* x   = (const float*)d_in[0];
    const int*   ei  = (const int*)d_in[1];
    const float* W1  = (const float*)d_in[2];
    const float* b1  = (const float*)d_in[3];
    const float* g1  = (const float*)d_in[4];
    const float* bt1 = (const float*)d_in[5];
    const float* W2  = (const float*)d_in[6];
    const float* b2  = (const float*)d_in[7];
    const float* g2  = (const float*)d_in[8];
    const float* bt2 = (const float*)d_in[9];
    float* out = (float*)d_out;

    const int* src = ei;
    const int* dst = ei + EE;

    __half2* hP = nullptr;
    float* aggP = nullptr;
    cudaGetSymbolAddress((void**)&hP, g_h);
    cudaGetSymbolAddress((void**)&aggP, g_agg);

    const int NB = (NN + 1023) / 1024;  // 98
    const int AGG_BLOCKS = 1184;

    zero_kernel<<<(NN + 255) / 256, 256>>>();
    hist_kernel<<<(EE + 255) / 256, 256>>>(dst);
    degscan_kernel<<<NB, 1024>>>(NB);
    scan_final_kernel<<<NB, 1024>>>();
    fill_kernel<<<(EE + 255) / 256, 256>>>(src, dst);

    // ---- layer 1 ----
    gemm_kernel<INF, 0><<<(NN + 127) / 128, 256>>>(x, W1, hP, 0);
    aggstats_kernel<<<AGG_BLOCKS, 256>>>(hP, b1, aggP, 0);
    bnprep_kernel<<<1, 64>>>(0, g1, bt1);

    // ---- layer 2 (BN+ReLU of layer 1 fused into A-tile load) ----
    gemm_kernel<HH, 1><<<(NN + 127) / 128, 256>>>(aggP, W2, hP, 0);
    aggstats_kernel<<<AGG_BLOCKS, 256>>>(hP, b2, aggP, 1);
    bnprep_kernel<<<1, 64>>>(1, g2, bt2);
    bnapply_kernel<<<(NN * 16 + 255) / 256, 256>>>(aggP, 1, out);
}

// round 6
// speedup vs baseline: 1.3149x; 1.3149x over previous
#include <cuda_runtime.h>
#include <cuda_bf16.h>
#include <cuda_fp16.h>
#include <math.h>
#include <stdint.h>

#define NN 100000
#define EE 1000000
#define INF 128
#define HH 64
#define BN_EPS 1e-5f

typedef unsigned long long ull;

// ---------------- scratch (device globals, no runtime alloc) ----------------
__device__ int   g_indeg[NN];
__device__ int   g_off[NN + 1];
__device__ int   g_cursor[NN];
__device__ int   g_csr[EE];
__device__ float g_dinv[NN];
__device__ int   g_bsum[128];
__device__ int   g_boff[128];
__device__ int   g_ticket;
__device__ float g_sum[2][HH];
__device__ float g_sq[2][HH];
__device__ float g_scale[2][HH];
__device__ float g_shift[2][HH];

__device__ float g_h[(size_t)NN * HH];    // GEMM output (fp32), pre-scaled by dinv[row]
__device__ float g_agg[(size_t)NN * HH];  // aggregation output (pre-BN)

// ---------------- graph build ----------------

__global__ void zero_kernel() {
    int i = blockIdx.x * blockDim.x + threadIdx.x;
    if (i < NN) g_indeg[i] = 0;
    if (i == 0) g_ticket = 0;
    if (i < HH) {
        g_sum[0][i] = 0.f; g_sum[1][i] = 0.f;
        g_sq[0][i]  = 0.f; g_sq[1][i]  = 0.f;
    }
}

__global__ void hist_kernel(const int* __restrict__ dst) {
    int e = blockIdx.x * blockDim.x + threadIdx.x;
    if (e < EE) atomicAdd(&g_indeg[dst[e]], 1);
}

__global__ void degscan_kernel(int nb) {
    __shared__ int sh[1024];
    __shared__ int isLast;
    int t = threadIdx.x;
    int idx = blockIdx.x * 1024 + t;
    int v = (idx < NN) ? g_indeg[idx] : 0;
    sh[t] = v;
    __syncthreads();
    for (int s = 512; s > 0; s >>= 1) {
        if (t < s) sh[t] += sh[t + s];
        __syncthreads();
    }
    if (t == 0) {
        g_bsum[blockIdx.x] = sh[0];
        __threadfence();
        isLast = (atomicAdd(&g_ticket, 1) == gridDim.x - 1);
    }
    __syncthreads();
    if (isLast && t < 128) {
        __shared__ int sc[128];
        int bv = (t < nb) ? g_bsum[t] : 0;
        sc[t] = bv;
        __syncthreads();
        for (int o = 1; o < 128; o <<= 1) {
            int a = (t >= o) ? sc[t - o] : 0;
            __syncthreads();
            sc[t] += a;
            __syncthreads();
        }
        if (t < nb) g_boff[t] = sc[t] - bv;
        if (t == nb - 1) g_off[NN] = sc[t];
    }
}

__global__ void scan_final_kernel() {
    __shared__ int sh[1024];
    int t = threadIdx.x;
    int idx = blockIdx.x * 1024 + t;
    int v = (idx < NN) ? g_indeg[idx] : 0;
    sh[t] = v;
    __syncthreads();
    for (int o = 1; o < 1024; o <<= 1) {
        int a = (t >= o) ? sh[t - o] : 0;
        __syncthreads();
        sh[t] += a;
        __syncthreads();
    }
    int excl = sh[t] - v;
    if (idx < NN) {
        int off = g_boff[blockIdx.x] + excl;
        g_off[idx] = off;
        g_cursor[idx] = off;
        g_dinv[idx] = rsqrtf((float)(v + 1));
    }
}

__global__ void fill_kernel(const int* __restrict__ src, const int* __restrict__ dst) {
    int e = blockIdx.x * blockDim.x + threadIdx.x;
    if (e < EE) {
        int d = dst[e];
        int p = atomicAdd(&g_cursor[d], 1);
        g_csr[p] = src[e];
    }
}

// ---------------- HMMA GEMM (mma.sync m16n8k16, fp16 in / fp32 accum) ----------------
// h[row] = dinv[row] * (bn_relu?(A[row]) @ W).  Block tile M=128 x N=64, full K in smem.
// As[128][K+8] fp16 (row-major, K contiguous).  Bs[64][K+8] fp16 = W^T (n rows, K contiguous).
// Row stride (K+8)*2 bytes == 16 mod 128 -> ldmatrix phases conflict-free.

__device__ __forceinline__ uint32_t smem_u32(const void* p) {
    uint32_t a;
    asm("{ .reg .u64 t; cvta.to.shared.u64 t, %1; cvt.u32.u64 %0, t; }" : "=r"(a) : "l"(p));
    return a;
}

__device__ __forceinline__ void ldmat_x4(uint32_t& r0, uint32_t& r1, uint32_t& r2, uint32_t& r3,
                                         uint32_t addr) {
    asm volatile("ldmatrix.sync.aligned.m8n8.x4.shared.b16 {%0,%1,%2,%3}, [%4];"
                 : "=r"(r0), "=r"(r1), "=r"(r2), "=r"(r3) : "r"(addr));
}

__device__ __forceinline__ void mma_16816(float& c0, float& c1, float& c2, float& c3,
                                          uint32_t a0, uint32_t a1, uint32_t a2, uint32_t a3,
                                          uint32_t b0, uint32_t b1) {
    asm volatile("mma.sync.aligned.m16n8k16.row.col.f32.f16.f16.f32 "
                 "{%0,%1,%2,%3}, {%4,%5,%6,%7}, {%8,%9}, {%0,%1,%2,%3};"
                 : "+f"(c0), "+f"(c1), "+f"(c2), "+f"(c3)
                 : "r"(a0), "r"(a1), "r"(a2), "r"(a3), "r"(b0), "r"(b1));
}

template <int K, int DO_BN>
__global__ __launch_bounds__(256, 2)
void mma_gemm_kernel(const float* __restrict__ A, const float* __restrict__ W,
                     float* __restrict__ C, int layer) {
    extern __shared__ char smem[];
    const int KS = K + 8;                 // padded row stride in halves
    const int A_OFF = 512;
    const int B_OFF = A_OFF + 128 * KS * 2;
    float* s_scale = (float*)(smem + 0);
    float* s_shift = (float*)(smem + 256);
    __half* As = (__half*)(smem + A_OFF);
    __half* Bs = (__half*)(smem + B_OFF);

    int t = threadIdx.x;
    int wid = t >> 5;
    int lane = t & 31;
    int m0 = blockIdx.x * 128;

    if (DO_BN) {
        if (t < 64) { s_scale[t] = g_scale[layer][t]; s_shift[t] = g_shift[layer][t]; }
        __syncthreads();
    }

    // ---- A tile: fp32 -> (BN+ReLU) -> fp16 ----
    const int QK = K / 4;
    for (int idx = t; idx < 128 * QK; idx += 256) {
        int r = idx / QK;
        int q = idx - r * QK;
        int k = q * 4;
        int row = m0 + r;
        float4 v = make_float4(0.f, 0.f, 0.f, 0.f);
        if (row < NN) v = *reinterpret_cast<const float4*>(A + (size_t)row * K + k);
        if (DO_BN) {
            v.x = fmaxf(fmaf(v.x, s_scale[k + 0], s_shift[k + 0]), 0.f);
            v.y = fmaxf(fmaf(v.y, s_scale[k + 1], s_shift[k + 1]), 0.f);
            v.z = fmaxf(fmaf(v.z, s_scale[k + 2], s_shift[k + 2]), 0.f);
            v.w = fmaxf(fmaf(v.w, s_scale[k + 3], s_shift[k + 3]), 0.f);
        }
        __half2 h01 = __floats2half2_rn(v.x, v.y);
        __half2 h23 = __floats2half2_rn(v.z, v.w);
        ull pk = (ull)(*reinterpret_cast<uint32_t*>(&h01)) |
                 ((ull)(*reinterpret_cast<uint32_t*>(&h23)) << 32);
        *reinterpret_cast<ull*>(&As[r * KS + k]) = pk;
    }

    // ---- B tile = W^T: Bs[n][k] = W[k][n] ----
    for (int idx = t; idx < K * 64; idx += 256) {
        int k = idx >> 6;
        int n = idx & 63;
        Bs[n * KS + k] = __float2half_rn(W[idx]);
    }
    __syncthreads();

    // ---- MMA: warp w owns rows [w*16, w*16+16), 8 n-blocks of 8 ----
    float acc[8][4];
#pragma unroll
    for (int nb = 0; nb < 8; nb++)
#pragma unroll
        for (int j = 0; j < 4; j++) acc[nb][j] = 0.f;

    uint32_t as_base = smem_u32(As);
    uint32_t bs_base = smem_u32(Bs);

    uint32_t a_row = wid * 16 + (lane & 15);
    uint32_t a_addr0 = as_base + (a_row * KS + (lane >> 4) * 8) * 2;
    uint32_t b_n = (lane & 7) + ((lane >> 4) & 1) * 8;
    uint32_t b_k = ((lane >> 3) & 1) * 8;
    uint32_t b_addr0 = bs_base + (b_n * KS + b_k) * 2;

#pragma unroll
    for (int ks = 0; ks < K / 16; ks++) {
        uint32_t a0, a1, a2, a3;
        ldmat_x4(a0, a1, a2, a3, a_addr0 + ks * 32);   // 16 halves = 32 bytes
#pragma unroll
        for (int nb2 = 0; nb2 < 4; nb2++) {
            uint32_t b0, b1, b2, b3;
            ldmat_x4(b0, b1, b2, b3, b_addr0 + (nb2 * 16 * KS + ks * 16) * 2);
            mma_16816(acc[nb2 * 2 + 0][0], acc[nb2 * 2 + 0][1], acc[nb2 * 2 + 0][2], acc[nb2 * 2 + 0][3],
                      a0, a1, a2, a3, b0, b1);
            mma_16816(acc[nb2 * 2 + 1][0], acc[nb2 * 2 + 1][1], acc[nb2 * 2 + 1][2], acc[nb2 * 2 + 1][3],
                      a0, a1, a2, a3, b2, b3);
        }
    }

    // ---- epilogue: c0,c1 -> (row g, cols 2t,2t+1); c2,c3 -> (row g+8) ----
    int g = lane >> 2;
    int tq = lane & 3;
    int row0 = m0 + wid * 16 + g;
    int row1 = row0 + 8;
    if (row0 < NN) {
        float di = g_dinv[row0];
#pragma unroll
        for (int nb = 0; nb < 8; nb++) {
            float2 o = make_float2(acc[nb][0] * di, acc[nb][1] * di);
            *reinterpret_cast<float2*>(C + (size_t)row0 * 64 + nb * 8 + tq * 2) = o;
        }
    }
    if (row1 < NN) {
        float di = g_dinv[row1];
#pragma unroll
        for (int nb = 0; nb < 8; nb++) {
            float2 o = make_float2(acc[nb][2] * di, acc[nb][3] * di);
            *reinterpret_cast<float2*>(C + (size_t)row1 * 64 + nb * 8 + tq * 2) = o;
        }
    }
}

// ---------------- aggregation (fp32) + fused BN statistics ----------------
__global__ void aggstats_kernel(const float* __restrict__ h, const float* __restrict__ bias,
                                float* __restrict__ out, int layer) {
    __shared__ float s_sum[64], s_sq[64];
    int t = threadIdx.x;
    if (t < 64) { s_sum[t] = 0.f; s_sq[t] = 0.f; }
    __syncthreads();
    int lane = t & 31;
    int warpId = blockIdx.x * (blockDim.x >> 5) + (t >> 5);
    int totalWarps = gridDim.x * (blockDim.x >> 5);
    float2 b = reinterpret_cast<const float2*>(bias)[lane];
    const float2* h2 = reinterpret_cast<const float2*>(h);
    float sx = 0.f, sy = 0.f, sxx = 0.f, syy = 0.f;

    for (int i = warpId; i < NN; i += totalWarps) {
        float di = g_dinv[i];
        float2 acc = h2[(size_t)i * 32 + lane];
        int e0 = g_off[i], e1 = g_off[i + 1];
        int j = e0;
        for (; j + 3 < e1; j += 4) {
            int s0 = g_csr[j], s1 = g_csr[j + 1], s2 = g_csr[j + 2], s3 = g_csr[j + 3];
            float2 v0 = h2[(size_t)s0 * 32 + lane];
            float2 v1 = h2[(size_t)s1 * 32 + lane];
            float2 v2 = h2[(size_t)s2 * 32 + lane];
            float2 v3 = h2[(size_t)s3 * 32 + lane];
            acc.x += (v0.x + v1.x) + (v2.x + v3.x);
            acc.y += (v0.y + v1.y) + (v2.y + v3.y);
        }
        for (; j < e1; j++) {
            float2 v = h2[(size_t)g_csr[j] * 32 + lane];
            acc.x += v.x; acc.y += v.y;
        }
        float ox = fmaf(acc.x, di, b.x);
        float oy = fmaf(acc.y, di, b.y);
        reinterpret_cast<float2*>(out)[(size_t)i * 32 + lane] = make_float2(ox, oy);
        sx += ox; sxx += ox * ox;
        sy += oy; syy += oy * oy;
    }
    atomicAdd(&s_sum[lane * 2 + 0], sx);
    atomicAdd(&s_sq [lane * 2 + 0], sxx);
    atomicAdd(&s_sum[lane * 2 + 1], sy);
    atomicAdd(&s_sq [lane * 2 + 1], syy);
    __syncthreads();
    if (t < 64) {
        atomicAdd(&g_sum[layer][t], s_sum[t]);
        atomicAdd(&g_sq[layer][t], s_sq[t]);
    }
}

__global__ void bnprep_kernel(int layer, const float* __restrict__ gamma,
                              const float* __restrict__ beta) {
    int c = threadIdx.x;
    if (c < HH) {
        float m   = g_sum[layer][c] * (1.0f / NN);
        float var = g_sq[layer][c] * (1.0f / NN) - m * m;
        float sc  = gamma[c] * rsqrtf(var + BN_EPS);
        g_scale[layer][c] = sc;
        g_shift[layer][c] = beta[c] - m * sc;
    }
}

__global__ void bnapply_kernel(const float* __restrict__ v, int layer,
                               float* __restrict__ out) {
    int idx = blockIdx.x * blockDim.x + threadIdx.x;
    if (idx >= NN * 16) return;
    float4 x = reinterpret_cast<const float4*>(v)[idx];
    int c = (idx & 15) * 4;
    x.x = fmaxf(fmaf(x.x, g_scale[layer][c + 0], g_shift[layer][c + 0]), 0.f);
    x.y = fmaxf(fmaf(x.y, g_scale[layer][c + 1], g_shift[layer][c + 1]), 0.f);
    x.z = fmaxf(fmaf(x.z, g_scale[layer][c + 2], g_shift[layer][c + 2]), 0.f);
    x.w = fmaxf(fmaf(x.w, g_scale[layer][c + 3], g_shift[layer][c + 3]), 0.f);
    reinterpret_cast<float4*>(out)[idx] = x;
}

// ---------------- launch ----------------
extern "C" void kernel_launch(void* const* d_in, const int* in_sizes, int n_in,
                              void* d_out, int out_size) {
    const float* x   = (const float*)d_in[0];
    const int*   ei  = (const int*)d_in[1];
    const float* W1  = (const float*)d_in[2];
    const float* b1  = (const float*)d_in[3];
    const float* g1  = (const float*)d_in[4];
    const float* bt1 = (const float*)d_in[5];
    const float* W2  = (const float*)d_in[6];
    const float* b2  = (const float*)d_in[7];
    const float* g2  = (const float*)d_in[8];
    const float* bt2 = (const float*)d_in[9];
    float* out = (float*)d_out;

    const int* src = ei;
    const int* dst = ei + EE;

    float *hP = nullptr, *aggP = nullptr;
    cudaGetSymbolAddress((void**)&hP, g_h);
    cudaGetSymbolAddress((void**)&aggP, g_agg);

    const int NB = (NN + 1023) / 1024;  // 98
    const int AGG_BLOCKS = 1184;
    const int SMEM1 = 512 + 128 * (INF + 8) * 2 + 64 * (INF + 8) * 2;  // 52736
    const int SMEM2 = 512 + 128 * (HH + 8) * 2 + 64 * (HH + 8) * 2;    // 28160

    cudaFuncSetAttribute(mma_gemm_kernel<INF, 0>,
                         cudaFuncAttributeMaxDynamicSharedMemorySize, SMEM1);
    cudaFuncSetAttribute(mma_gemm_kernel<HH, 1>,
                         cudaFuncAttributeMaxDynamicSharedMemorySize, SMEM2);

    zero_kernel<<<(NN + 255) / 256, 256>>>();
    hist_kernel<<<(EE + 255) / 256, 256>>>(dst);
    degscan_kernel<<<NB, 1024>>>(NB);
    scan_final_kernel<<<NB, 1024>>>();
    fill_kernel<<<(EE + 255) / 256, 256>>>(src, dst);

    // ---- layer 1 ----
    mma_gemm_kernel<INF, 0><<<(NN + 127) / 128, 256, SMEM1>>>(x, W1, hP, 0);
    aggstats_kernel<<<AGG_BLOCKS, 256>>>(hP, b1, aggP, 0);
    bnprep_kernel<<<1, 64>>>(0, g1, bt1);

    // ---- layer 2: BN+ReLU of layer 1 fused into A-tile load, using LAYER-0 params ----
    mma_gemm_kernel<HH, 1><<<(NN + 127) / 128, 256, SMEM2>>>(aggP, W2, hP, 0);
    aggstats_kernel<<<AGG_BLOCKS, 256>>>(hP, b2, aggP, 1);
    bnprep_kernel<<<1, 64>>>(1, g2, bt2);
    bnapply_kernel<<<(NN * 16 + 255) / 256, 256>>>(aggP, 1, out);
}

// round 7
// speedup vs baseline: 1.3763x; 1.0467x over previous
#include <cuda_runtime.h>
#include <cuda_bf16.h>
#include <cuda_fp16.h>
#include <math.h>
#include <stdint.h>

#define NN 100000
#define EE 1000000
#define INF 128
#define HH 64
#define BN_EPS 1e-5f

typedef unsigned long long ull;

// ---------------- scratch (device globals, no runtime alloc) ----------------
__device__ int   g_indeg[NN];
__device__ int   g_off[NN + 1];
__device__ int   g_cursor[NN];
__device__ int   g_csr[EE];
__device__ float g_dinv[NN];
__device__ int   g_bsum[128];
__device__ int   g_boff[128];
__device__ int   g_ticket;
__device__ int   g_flag;
__device__ float g_sum[2][HH];
__device__ float g_sq[2][HH];
__device__ float g_scale[2][HH];
__device__ float g_shift[2][HH];

__device__ __half2 g_h[(size_t)NN * 32];   // GEMM output (fp16 pairs), pre-scaled by dinv[row]
__device__ float   g_agg[(size_t)NN * HH]; // aggregation output (pre-BN, fp32)

// ---------------- graph build ----------------

__global__ void zero_kernel() {
    int i = blockIdx.x * blockDim.x + threadIdx.x;
    if (i < NN) g_indeg[i] = 0;
    if (i == 0) { g_ticket = 0; g_flag = 0; }
    if (i < HH) {
        g_sum[0][i] = 0.f; g_sum[1][i] = 0.f;
        g_sq[0][i]  = 0.f; g_sq[1][i]  = 0.f;
    }
}

__global__ void hist_kernel(const int* __restrict__ dst) {
    int e = blockIdx.x * blockDim.x + threadIdx.x;
    if (e < EE) atomicAdd(&g_indeg[dst[e]], 1);
}

// fused: per-block inclusive scan + cross-block scan (last-block election) + finalize.
// 98 blocks of 1024 — all resident on 148 SMs, so the flag spin cannot deadlock.
__global__ void degscan_kernel(int nb) {
    __shared__ int sh[1024];
    __shared__ int amLast;
    int t = threadIdx.x;
    int b = blockIdx.x;
    int idx = b * 1024 + t;
    int v = (idx < NN) ? g_indeg[idx] : 0;
    sh[t] = v;
    __syncthreads();
    for (int o = 1; o < 1024; o <<= 1) {
        int a = (t >= o) ? sh[t - o] : 0;
        __syncthreads();
        sh[t] += a;
        __syncthreads();
    }
    int incl = sh[t];                       // inclusive scan within block
    if (t == 1023) {
        g_bsum[b] = incl;                   // block total
        __threadfence();
        amLast = (atomicAdd(&g_ticket, 1) == gridDim.x - 1);
    }
    __syncthreads();
    if (amLast) {
        int bv = (t < nb) ? g_bsum[t] : 0;
        sh[t] = (t < 128) ? bv : 0;
        __syncthreads();
        for (int o = 1; o < 128; o <<= 1) {
            int a = (t >= o && t < 128) ? sh[t - o] : 0;
            __syncthreads();
            if (t < 128) sh[t] += a;
            __syncthreads();
        }
        if (t < nb) g_boff[t] = sh[t] - bv;     // exclusive
        if (t == nb - 1) g_off[NN] = sh[t];     // == EE
        __threadfence();
        if (t == 0) atomicExch(&g_flag, 1);
    }
    if (t == 0) {
        while (atomicAdd(&g_flag, 0) == 0) {}
    }
    __syncthreads();
    if (idx < NN) {
        int off = g_boff[b] + incl - v;         // exclusive global offset
        g_off[idx] = off;
        g_cursor[idx] = off;
        g_dinv[idx] = rsqrtf((float)(v + 1));   // deg = indeg + self-loop
    }
}

__global__ void fill_kernel(const int* __restrict__ src, const int* __restrict__ dst) {
    int e = blockIdx.x * blockDim.x + threadIdx.x;
    if (e < EE) {
        int d = dst[e];
        int p = atomicAdd(&g_cursor[d], 1);
        g_csr[p] = src[e];
    }
}

// ---------------- HMMA GEMM (mma.sync m16n8k16, fp16 in / fp32 accum) ----------------
// h[row] = fp16( dinv[row] * (bn_relu?(A[row]) @ W) ).  Block tile M=128 x N=64.

__device__ __forceinline__ uint32_t smem_u32(const void* p) {
    uint32_t a;
    asm("{ .reg .u64 t; cvta.to.shared.u64 t, %1; cvt.u32.u64 %0, t; }" : "=r"(a) : "l"(p));
    return a;
}

__device__ __forceinline__ void ldmat_x4(uint32_t& r0, uint32_t& r1, uint32_t& r2, uint32_t& r3,
                                         uint32_t addr) {
    asm volatile("ldmatrix.sync.aligned.m8n8.x4.shared.b16 {%0,%1,%2,%3}, [%4];"
                 : "=r"(r0), "=r"(r1), "=r"(r2), "=r"(r3) : "r"(addr));
}

__device__ __forceinline__ void mma_16816(float& c0, float& c1, float& c2, float& c3,
                                          uint32_t a0, uint32_t a1, uint32_t a2, uint32_t a3,
                                          uint32_t b0, uint32_t b1) {
    asm volatile("mma.sync.aligned.m16n8k16.row.col.f32.f16.f16.f32 "
                 "{%0,%1,%2,%3}, {%4,%5,%6,%7}, {%8,%9}, {%0,%1,%2,%3};"
                 : "+f"(c0), "+f"(c1), "+f"(c2), "+f"(c3)
                 : "r"(a0), "r"(a1), "r"(a2), "r"(a3), "r"(b0), "r"(b1));
}

template <int K, int DO_BN>
__global__ __launch_bounds__(256, 2)
void mma_gemm_kernel(const float* __restrict__ A, const float* __restrict__ W,
                     __half2* __restrict__ C, int layer) {
    extern __shared__ char smem[];
    const int KS = K + 8;                 // padded row stride in halves
    const int A_OFF = 512;
    const int B_OFF = A_OFF + 128 * KS * 2;
    float* s_scale = (float*)(smem + 0);
    float* s_shift = (float*)(smem + 256);
    __half* As = (__half*)(smem + A_OFF);
    __half* Bs = (__half*)(smem + B_OFF);

    int t = threadIdx.x;
    int wid = t >> 5;
    int lane = t & 31;
    int m0 = blockIdx.x * 128;

    if (DO_BN) {
        if (t < 64) { s_scale[t] = g_scale[layer][t]; s_shift[t] = g_shift[layer][t]; }
        __syncthreads();
    }

    // ---- A tile: fp32 -> (BN+ReLU) -> fp16 ----
    const int QK = K / 4;
    for (int idx = t; idx < 128 * QK; idx += 256) {
        int r = idx / QK;
        int q = idx - r * QK;
        int k = q * 4;
        int row = m0 + r;
        float4 v = make_float4(0.f, 0.f, 0.f, 0.f);
        if (row < NN) v = *reinterpret_cast<const float4*>(A + (size_t)row * K + k);
        if (DO_BN) {
            v.x = fmaxf(fmaf(v.x, s_scale[k + 0], s_shift[k + 0]), 0.f);
            v.y = fmaxf(fmaf(v.y, s_scale[k + 1], s_shift[k + 1]), 0.f);
            v.z = fmaxf(fmaf(v.z, s_scale[k + 2], s_shift[k + 2]), 0.f);
            v.w = fmaxf(fmaf(v.w, s_scale[k + 3], s_shift[k + 3]), 0.f);
        }
        __half2 h01 = __floats2half2_rn(v.x, v.y);
        __half2 h23 = __floats2half2_rn(v.z, v.w);
        ull pk = (ull)(*reinterpret_cast<uint32_t*>(&h01)) |
                 ((ull)(*reinterpret_cast<uint32_t*>(&h23)) << 32);
        *reinterpret_cast<ull*>(&As[r * KS + k]) = pk;
    }

    // ---- B tile = W^T: Bs[n][k] = W[k][n] ----
    for (int idx = t; idx < K * 64; idx += 256) {
        int k = idx >> 6;
        int n = idx & 63;
        Bs[n * KS + k] = __float2half_rn(W[idx]);
    }
    __syncthreads();

    // ---- MMA: warp w owns rows [w*16, w*16+16), 8 n-blocks of 8 ----
    float acc[8][4];
#pragma unroll
    for (int nb = 0; nb < 8; nb++)
#pragma unroll
        for (int j = 0; j < 4; j++) acc[nb][j] = 0.f;

    uint32_t as_base = smem_u32(As);
    uint32_t bs_base = smem_u32(Bs);

    uint32_t a_row = wid * 16 + (lane & 15);
    uint32_t a_addr0 = as_base + (a_row * KS + (lane >> 4) * 8) * 2;
    uint32_t b_n = (lane & 7) + ((lane >> 4) & 1) * 8;
    uint32_t b_k = ((lane >> 3) & 1) * 8;
    uint32_t b_addr0 = bs_base + (b_n * KS + b_k) * 2;

#pragma unroll
    for (int ks = 0; ks < K / 16; ks++) {
        uint32_t a0, a1, a2, a3;
        ldmat_x4(a0, a1, a2, a3, a_addr0 + ks * 32);
#pragma unroll
        for (int nb2 = 0; nb2 < 4; nb2++) {
            uint32_t b0, b1, b2, b3;
            ldmat_x4(b0, b1, b2, b3, b_addr0 + (nb2 * 16 * KS + ks * 16) * 2);
            mma_16816(acc[nb2 * 2 + 0][0], acc[nb2 * 2 + 0][1], acc[nb2 * 2 + 0][2], acc[nb2 * 2 + 0][3],
                      a0, a1, a2, a3, b0, b1);
            mma_16816(acc[nb2 * 2 + 1][0], acc[nb2 * 2 + 1][1], acc[nb2 * 2 + 1][2], acc[nb2 * 2 + 1][3],
                      a0, a1, a2, a3, b2, b3);
        }
    }

    // ---- epilogue: scale by dinv, convert to fp16 pairs, store ----
    int g = lane >> 2;
    int tq = lane & 3;
    int row0 = m0 + wid * 16 + g;
    int row1 = row0 + 8;
    if (row0 < NN) {
        float di = g_dinv[row0];
#pragma unroll
        for (int nb = 0; nb < 8; nb++)
            C[(size_t)row0 * 32 + nb * 4 + tq] = __floats2half2_rn(acc[nb][0] * di, acc[nb][1] * di);
    }
    if (row1 < NN) {
        float di = g_dinv[row1];
#pragma unroll
        for (int nb = 0; nb < 8; nb++)
            C[(size_t)row1 * 32 + nb * 4 + tq] = __floats2half2_rn(acc[nb][2] * di, acc[nb][3] * di);
    }
}

// ---------------- aggregation (fp16 gather, fp32 accum) + fused BN statistics ----------------
__global__ void aggstats_kernel(const __half2* __restrict__ h, const float* __restrict__ bias,
                                float* __restrict__ out, int layer) {
    __shared__ float s_sum[64], s_sq[64];
    int t = threadIdx.x;
    if (t < 64) { s_sum[t] = 0.f; s_sq[t] = 0.f; }
    __syncthreads();
    int lane = t & 31;
    int warpId = blockIdx.x * (blockDim.x >> 5) + (t >> 5);
    int totalWarps = gridDim.x * (blockDim.x >> 5);
    float2 b = reinterpret_cast<const float2*>(bias)[lane];
    float sx = 0.f, sy = 0.f, sxx = 0.f, syy = 0.f;

    for (int i = warpId; i < NN; i += totalWarps) {
        float di = g_dinv[i];
        float2 acc = __half22float2(h[(size_t)i * 32 + lane]);  // self-loop (pre-scaled)
        int e0 = g_off[i], e1 = g_off[i + 1];
        int j = e0;
        for (; j + 3 < e1; j += 4) {
            int s0 = g_csr[j], s1 = g_csr[j + 1], s2 = g_csr[j + 2], s3 = g_csr[j + 3];
            float2 v0 = __half22float2(h[(size_t)s0 * 32 + lane]);
            float2 v1 = __half22float2(h[(size_t)s1 * 32 + lane]);
            float2 v2 = __half22float2(h[(size_t)s2 * 32 + lane]);
            float2 v3 = __half22float2(h[(size_t)s3 * 32 + lane]);
            acc.x += (v0.x + v1.x) + (v2.x + v3.x);
            acc.y += (v0.y + v1.y) + (v2.y + v3.y);
        }
        for (; j < e1; j++) {
            float2 v = __half22float2(h[(size_t)g_csr[j] * 32 + lane]);
            acc.x += v.x; acc.y += v.y;
        }
        float ox = fmaf(acc.x, di, b.x);
        float oy = fmaf(acc.y, di, b.y);
        reinterpret_cast<float2*>(out)[(size_t)i * 32 + lane] = make_float2(ox, oy);
        sx += ox; sxx += ox * ox;
        sy += oy; syy += oy * oy;
    }
    atomicAdd(&s_sum[lane * 2 + 0], sx);
    atomicAdd(&s_sq [lane * 2 + 0], sxx);
    atomicAdd(&s_sum[lane * 2 + 1], sy);
    atomicAdd(&s_sq [lane * 2 + 1], syy);
    __syncthreads();
    if (t < 64) {
        atomicAdd(&g_sum[layer][t], s_sum[t]);
        atomicAdd(&g_sq[layer][t], s_sq[t]);
    }
}

__global__ void bnprep_kernel(int layer, const float* __restrict__ gamma,
                              const float* __restrict__ beta) {
    int c = threadIdx.x;
    if (c < HH) {
        float m   = g_sum[layer][c] * (1.0f / NN);
        float var = g_sq[layer][c] * (1.0f / NN) - m * m;
        float sc  = gamma[c] * rsqrtf(var + BN_EPS);
        g_scale[layer][c] = sc;
        g_shift[layer][c] = beta[c] - m * sc;
    }
}

__global__ void bnapply_kernel(const float* __restrict__ v, int layer,
                               float* __restrict__ out) {
    int idx = blockIdx.x * blockDim.x + threadIdx.x;
    if (idx >= NN * 16) return;
    float4 x = reinterpret_cast<const float4*>(v)[idx];
    int c = (idx & 15) * 4;
    x.x = fmaxf(fmaf(x.x, g_scale[layer][c + 0], g_shift[layer][c + 0]), 0.f);
    x.y = fmaxf(fmaf(x.y, g_scale[layer][c + 1], g_shift[layer][c + 1]), 0.f);
    x.z = fmaxf(fmaf(x.z, g_scale[layer][c + 2], g_shift[layer][c + 2]), 0.f);
    x.w = fmaxf(fmaf(x.w, g_scale[layer][c + 3], g_shift[layer][c + 3]), 0.f);
    reinterpret_cast<float4*>(out)[idx] = x;
}

// ---------------- launch ----------------
extern "C" void kernel_launch(void* const* d_in, const int* in_sizes, int n_in,
                              void* d_out, int out_size) {
    const float* x   = (const float*)d_in[0];
    const int*   ei  = (const int*)d_in[1];
    const float* W1  = (const float*)d_in[2];
    const float* b1  = (const float*)d_in[3];
    const float* g1  = (const float*)d_in[4];
    const float* bt1 = (const float*)d_in[5];
    const float* W2  = (const float*)d_in[6];
    const float* b2  = (const float*)d_in[7];
    const float* g2  = (const float*)d_in[8];
    const float* bt2 = (const float*)d_in[9];
    float* out = (float*)d_out;

    const int* src = ei;
    const int* dst = ei + EE;

    __half2* hP = nullptr;
    float* aggP = nullptr;
    cudaGetSymbolAddress((void**)&hP, g_h);
    cudaGetSymbolAddress((void**)&aggP, g_agg);

    const int NB = (NN + 1023) / 1024;  // 98
    const int AGG_BLOCKS = 1184;
    const int SMEM1 = 512 + 128 * (INF + 8) * 2 + 64 * (INF + 8) * 2;  // 52736
    const int SMEM2 = 512 + 128 * (HH + 8) * 2 + 64 * (HH + 8) * 2;    // 28160

    cudaFuncSetAttribute(mma_gemm_kernel<INF, 0>,
                         cudaFuncAttributeMaxDynamicSharedMemorySize, SMEM1);
    cudaFuncSetAttribute(mma_gemm_kernel<HH, 1>,
                         cudaFuncAttributeMaxDynamicSharedMemorySize, SMEM2);

    zero_kernel<<<(NN + 255) / 256, 256>>>();
    hist_kernel<<<(EE + 255) / 256, 256>>>(dst);
    degscan_kernel<<<NB, 1024>>>(NB);
    fill_kernel<<<(EE + 255) / 256, 256>>>(src, dst);

    // ---- layer 1 ----
    mma_gemm_kernel<INF, 0><<<(NN + 127) / 128, 256, SMEM1>>>(x, W1, hP, 0);
    aggstats_kernel<<<AGG_BLOCKS, 256>>>(hP, b1, aggP, 0);
    bnprep_kernel<<<1, 64>>>(0, g1, bt1);

    // ---- layer 2: BN+ReLU of layer 1 fused into A-tile load (layer-0 params) ----
    mma_gemm_kernel<HH, 1><<<(NN + 127) / 128, 256, SMEM2>>>(aggP, W2, hP, 0);
    aggstats_kernel<<<AGG_BLOCKS, 256>>>(hP, b2, aggP, 1);
    bnprep_kernel<<<1, 64>>>(1, g2, bt2);
    bnapply_kernel<<<(NN * 16 + 255) / 256, 256>>>(aggP, 1, out);
}

// round 8
// speedup vs baseline: 1.3958x; 1.0142x over previous
#include <cuda_runtime.h>
#include <cuda_bf16.h>
#include <cuda_fp16.h>
#include <math.h>
#include <stdint.h>

#define NN 100000
#define EE 1000000
#define INF 128
#define HH 64
#define BN_EPS 1e-5f

typedef unsigned long long ull;

// ---------------- scratch (device globals, no runtime alloc) ----------------
__device__ int   g_indeg[NN];
__device__ int   g_off[NN + 1];
__device__ int   g_rank[EE];
__device__ int   g_csr[EE];
__device__ float g_dinv[NN];
__device__ int   g_bsum[128];
__device__ int   g_boff[128];
__device__ int   g_ticket;
__device__ int   g_flag;
__device__ float g_sum[2][HH];
__device__ float g_sq[2][HH];

__device__ __half2 g_h[(size_t)NN * 32];   // GEMM output (fp16 pairs), pre-scaled by dinv[row]
__device__ float   g_agg[(size_t)NN * HH]; // aggregation output (pre-BN, fp32)

// ---------------- graph build ----------------

__global__ void zero_kernel() {
    int i = blockIdx.x * blockDim.x + threadIdx.x;
    if (i < NN) g_indeg[i] = 0;
    if (i == 0) { g_ticket = 0; g_flag = 0; }
    if (i < HH) {
        g_sum[0][i] = 0.f; g_sum[1][i] = 0.f;
        g_sq[0][i]  = 0.f; g_sq[1][i]  = 0.f;
    }
}

// histogram + per-edge rank (the atomic's return value IS the rank)
__global__ void hist_kernel(const int* __restrict__ dst) {
    int e = blockIdx.x * blockDim.x + threadIdx.x;
    if (e < EE) g_rank[e] = atomicAdd(&g_indeg[dst[e]], 1);
}

// fused: per-block inclusive scan + cross-block scan (last-block election) + finalize.
// 98 blocks of 1024 — all resident on 148 SMs, so the flag spin cannot deadlock.
__global__ void degscan_kernel(int nb) {
    __shared__ int sh[1024];
    __shared__ int amLast;
    int t = threadIdx.x;
    int b = blockIdx.x;
    int idx = b * 1024 + t;
    int v = (idx < NN) ? g_indeg[idx] : 0;
    sh[t] = v;
    __syncthreads();
    for (int o = 1; o < 1024; o <<= 1) {
        int a = (t >= o) ? sh[t - o] : 0;
        __syncthreads();
        sh[t] += a;
        __syncthreads();
    }
    int incl = sh[t];
    if (t == 1023) {
        g_bsum[b] = incl;
        __threadfence();
        amLast = (atomicAdd(&g_ticket, 1) == gridDim.x - 1);
    }
    __syncthreads();
    if (amLast) {
        int bv = (t < nb) ? g_bsum[t] : 0;
        sh[t] = (t < 128) ? bv : 0;
        __syncthreads();
        for (int o = 1; o < 128; o <<= 1) {
            int a = (t >= o && t < 128) ? sh[t - o] : 0;
            __syncthreads();
            if (t < 128) sh[t] += a;
            __syncthreads();
        }
        if (t < nb) g_boff[t] = sh[t] - bv;
        if (t == nb - 1) g_off[NN] = sh[t];
        __threadfence();
        if (t == 0) atomicExch(&g_flag, 1);
    }
    if (t == 0) {
        while (atomicAdd(&g_flag, 0) == 0) {}
    }
    __syncthreads();
    if (idx < NN) {
        int off = g_boff[b] + incl - v;
        g_off[idx] = off;
        g_dinv[idx] = rsqrtf((float)(v + 1));   // deg = indeg + self-loop
    }
}

// atomic-free fill: pos = off[dst] + rank[e]
__global__ void fill_kernel(const int* __restrict__ src, const int* __restrict__ dst) {
    int e = blockIdx.x * blockDim.x + threadIdx.x;
    if (e < EE) g_csr[g_off[dst[e]] + g_rank[e]] = src[e];
}

// ---------------- HMMA GEMM (mma.sync m16n8k16, fp16 in / fp32 accum) ----------------
// h[row] = fp16( dinv[row] * (bn_relu?(A[row]) @ W) ).  Block tile M=128 x N=64.
// DO_BN: scale/shift computed in-block from g_sum[0]/g_sq[0] + gamma/beta (bnprep fused).

__device__ __forceinline__ uint32_t smem_u32(const void* p) {
    uint32_t a;
    asm("{ .reg .u64 t; cvta.to.shared.u64 t, %1; cvt.u32.u64 %0, t; }" : "=r"(a) : "l"(p));
    return a;
}

__device__ __forceinline__ void ldmat_x4(uint32_t& r0, uint32_t& r1, uint32_t& r2, uint32_t& r3,
                                         uint32_t addr) {
    asm volatile("ldmatrix.sync.aligned.m8n8.x4.shared.b16 {%0,%1,%2,%3}, [%4];"
                 : "=r"(r0), "=r"(r1), "=r"(r2), "=r"(r3) : "r"(addr));
}

__device__ __forceinline__ void mma_16816(float& c0, float& c1, float& c2, float& c3,
                                          uint32_t a0, uint32_t a1, uint32_t a2, uint32_t a3,
                                          uint32_t b0, uint32_t b1) {
    asm volatile("mma.sync.aligned.m16n8k16.row.col.f32.f16.f16.f32 "
                 "{%0,%1,%2,%3}, {%4,%5,%6,%7}, {%8,%9}, {%0,%1,%2,%3};"
                 : "+f"(c0), "+f"(c1), "+f"(c2), "+f"(c3)
                 : "r"(a0), "r"(a1), "r"(a2), "r"(a3), "r"(b0), "r"(b1));
}

template <int K, int DO_BN>
__global__ __launch_bounds__(256, 2)
void mma_gemm_kernel(const float* __restrict__ A, const float* __restrict__ W,
                     __half2* __restrict__ C,
                     const float* __restrict__ gamma, const float* __restrict__ beta) {
    extern __shared__ char smem[];
    const int KS = K + 8;
    const int A_OFF = 512;
    const int B_OFF = A_OFF + 128 * KS * 2;
    float* s_scale = (float*)(smem + 0);
    float* s_shift = (float*)(smem + 256);
    __half* As = (__half*)(smem + A_OFF);
    __half* Bs = (__half*)(smem + B_OFF);

    int t = threadIdx.x;
    int wid = t >> 5;
    int lane = t & 31;
    int m0 = blockIdx.x * 128;

    if (DO_BN) {
        if (t < 64) {
            float m   = g_sum[0][t] * (1.0f / NN);
            float var = g_sq[0][t] * (1.0f / NN) - m * m;
            float sc  = gamma[t] * rsqrtf(var + BN_EPS);
            s_scale[t] = sc;
            s_shift[t] = beta[t] - m * sc;
        }
        __syncthreads();
    }

    // ---- A tile: fp32 -> (BN+ReLU) -> fp16 ----
    const int QK = K / 4;
    for (int idx = t; idx < 128 * QK; idx += 256) {
        int r = idx / QK;
        int q = idx - r * QK;
        int k = q * 4;
        int row = m0 + r;
        float4 v = make_float4(0.f, 0.f, 0.f, 0.f);
        if (row < NN) v = *reinterpret_cast<const float4*>(A + (size_t)row * K + k);
        if (DO_BN) {
            v.x = fmaxf(fmaf(v.x, s_scale[k + 0], s_shift[k + 0]), 0.f);
            v.y = fmaxf(fmaf(v.y, s_scale[k + 1], s_shift[k + 1]), 0.f);
            v.z = fmaxf(fmaf(v.z, s_scale[k + 2], s_shift[k + 2]), 0.f);
            v.w = fmaxf(fmaf(v.w, s_scale[k + 3], s_shift[k + 3]), 0.f);
        }
        __half2 h01 = __floats2half2_rn(v.x, v.y);
        __half2 h23 = __floats2half2_rn(v.z, v.w);
        ull pk = (ull)(*reinterpret_cast<uint32_t*>(&h01)) |
                 ((ull)(*reinterpret_cast<uint32_t*>(&h23)) << 32);
        *reinterpret_cast<ull*>(&As[r * KS + k]) = pk;
    }

    // ---- B tile = W^T: Bs[n][k] = W[k][n] ----
    for (int idx = t; idx < K * 64; idx += 256) {
        int k = idx >> 6;
        int n = idx & 63;
        Bs[n * KS + k] = __float2half_rn(W[idx]);
    }
    __syncthreads();

    float acc[8][4];
#pragma unroll
    for (int nb = 0; nb < 8; nb++)
#pragma unroll
        for (int j = 0; j < 4; j++) acc[nb][j] = 0.f;

    uint32_t as_base = smem_u32(As);
    uint32_t bs_base = smem_u32(Bs);

    uint32_t a_row = wid * 16 + (lane & 15);
    uint32_t a_addr0 = as_base + (a_row * KS + (lane >> 4) * 8) * 2;
    uint32_t b_n = (lane & 7) + ((lane >> 4) & 1) * 8;
    uint32_t b_k = ((lane >> 3) & 1) * 8;
    uint32_t b_addr0 = bs_base + (b_n * KS + b_k) * 2;

#pragma unroll
    for (int ks = 0; ks < K / 16; ks++) {
        uint32_t a0, a1, a2, a3;
        ldmat_x4(a0, a1, a2, a3, a_addr0 + ks * 32);
#pragma unroll
        for (int nb2 = 0; nb2 < 4; nb2++) {
            uint32_t b0, b1, b2, b3;
            ldmat_x4(b0, b1, b2, b3, b_addr0 + (nb2 * 16 * KS + ks * 16) * 2);
            mma_16816(acc[nb2 * 2 + 0][0], acc[nb2 * 2 + 0][1], acc[nb2 * 2 + 0][2], acc[nb2 * 2 + 0][3],
                      a0, a1, a2, a3, b0, b1);
            mma_16816(acc[nb2 * 2 + 1][0], acc[nb2 * 2 + 1][1], acc[nb2 * 2 + 1][2], acc[nb2 * 2 + 1][3],
                      a0, a1, a2, a3, b2, b3);
        }
    }

    int g = lane >> 2;
    int tq = lane & 3;
    int row0 = m0 + wid * 16 + g;
    int row1 = row0 + 8;
    if (row0 < NN) {
        float di = g_dinv[row0];
#pragma unroll
        for (int nb = 0; nb < 8; nb++)
            C[(size_t)row0 * 32 + nb * 4 + tq] = __floats2half2_rn(acc[nb][0] * di, acc[nb][1] * di);
    }
    if (row1 < NN) {
        float di = g_dinv[row1];
#pragma unroll
        for (int nb = 0; nb < 8; nb++)
            C[(size_t)row1 * 32 + nb * 4 + tq] = __floats2half2_rn(acc[nb][2] * di, acc[nb][3] * di);
    }
}

// ---------------- aggregation (fp16 gather, fp32 accum) + fused BN statistics ----------------
__global__ void aggstats_kernel(const __half2* __restrict__ h, const float* __restrict__ bias,
                                float* __restrict__ out, int layer) {
    __shared__ float s_sum[64], s_sq[64];
    int t = threadIdx.x;
    if (t < 64) { s_sum[t] = 0.f; s_sq[t] = 0.f; }
    __syncthreads();
    int lane = t & 31;
    int warpId = blockIdx.x * (blockDim.x >> 5) + (t >> 5);
    int totalWarps = gridDim.x * (blockDim.x >> 5);
    float2 b = reinterpret_cast<const float2*>(bias)[lane];
    float sx = 0.f, sy = 0.f, sxx = 0.f, syy = 0.f;

    for (int i = warpId; i < NN; i += totalWarps) {
        float di = g_dinv[i];
        float2 acc = __half22float2(h[(size_t)i * 32 + lane]);
        int e0 = g_off[i], e1 = g_off[i + 1];
        int j = e0;
        for (; j + 3 < e1; j += 4) {
            int s0 = g_csr[j], s1 = g_csr[j + 1], s2 = g_csr[j + 2], s3 = g_csr[j + 3];
            float2 v0 = __half22float2(h[(size_t)s0 * 32 + lane]);
            float2 v1 = __half22float2(h[(size_t)s1 * 32 + lane]);
            float2 v2 = __half22float2(h[(size_t)s2 * 32 + lane]);
            float2 v3 = __half22float2(h[(size_t)s3 * 32 + lane]);
            acc.x += (v0.x + v1.x) + (v2.x + v3.x);
            acc.y += (v0.y + v1.y) + (v2.y + v3.y);
        }
        for (; j < e1; j++) {
            float2 v = __half22float2(h[(size_t)g_csr[j] * 32 + lane]);
            acc.x += v.x; acc.y += v.y;
        }
        float ox = fmaf(acc.x, di, b.x);
        float oy = fmaf(acc.y, di, b.y);
        reinterpret_cast<float2*>(out)[(size_t)i * 32 + lane] = make_float2(ox, oy);
        sx += ox; sxx += ox * ox;
        sy += oy; syy += oy * oy;
    }
    atomicAdd(&s_sum[lane * 2 + 0], sx);
    atomicAdd(&s_sq [lane * 2 + 0], sxx);
    atomicAdd(&s_sum[lane * 2 + 1], sy);
    atomicAdd(&s_sq [lane * 2 + 1], syy);
    __syncthreads();
    if (t < 64) {
        atomicAdd(&g_sum[layer][t], s_sum[t]);
        atomicAdd(&g_sq[layer][t], s_sq[t]);
    }
}

// BN apply with in-block prep (bnprep fused): scale/shift from g_sum[1]/g_sq[1]
__global__ void bnapply_kernel(const float* __restrict__ v,
                               const float* __restrict__ gamma, const float* __restrict__ beta,
                               float* __restrict__ out) {
    __shared__ float sc[64], sf[64];
    int t = threadIdx.x;
    if (t < 64) {
        float m   = g_sum[1][t] * (1.0f / NN);
        float var = g_sq[1][t] * (1.0f / NN) - m * m;
        float s   = gamma[t] * rsqrtf(var + BN_EPS);
        sc[t] = s;
        sf[t] = beta[t] - m * s;
    }
    __syncthreads();
    int idx = blockIdx.x * blockDim.x + t;
    if (idx >= NN * 16) return;
    float4 x = reinterpret_cast<const float4*>(v)[idx];
    int c = (idx & 15) * 4;
    x.x = fmaxf(fmaf(x.x, sc[c + 0], sf[c + 0]), 0.f);
    x.y = fmaxf(fmaf(x.y, sc[c + 1], sf[c + 1]), 0.f);
    x.z = fmaxf(fmaf(x.z, sc[c + 2], sf[c + 2]), 0.f);
    x.w = fmaxf(fmaf(x.w, sc[c + 3], sf[c + 3]), 0.f);
    reinterpret_cast<float4*>(out)[idx] = x;
}

// ---------------- launch ----------------
extern "C" void kernel_launch(void* const* d_in, const int* in_sizes, int n_in,
                              void* d_out, int out_size) {
    const float* x   = (const float*)d_in[0];
    const int*   ei  = (const int*)d_in[1];
    const float* W1  = (const float*)d_in[2];
    const float* b1  = (const float*)d_in[3];
    const float* g1  = (const float*)d_in[4];
    const float* bt1 = (const float*)d_in[5];
    const float* W2  = (const float*)d_in[6];
    const float* b2  = (const float*)d_in[7];
    const float* g2  = (const float*)d_in[8];
    const float* bt2 = (const float*)d_in[9];
    float* out = (float*)d_out;

    const int* src = ei;
    const int* dst = ei + EE;

    __half2* hP = nullptr;
    float* aggP = nullptr;
    cudaGetSymbolAddress((void**)&hP, g_h);
    cudaGetSymbolAddress((void**)&aggP, g_agg);

    const int NB = (NN + 1023) / 1024;  // 98
    const int AGG_BLOCKS = 1184;
    const int SMEM1 = 512 + 128 * (INF + 8) * 2 + 64 * (INF + 8) * 2;  // 52736
    const int SMEM2 = 512 + 128 * (HH + 8) * 2 + 64 * (HH + 8) * 2;    // 28160

    cudaFuncSetAttribute(mma_gemm_kernel<INF, 0>,
                         cudaFuncAttributeMaxDynamicSharedMemorySize, SMEM1);
    cudaFuncSetAttribute(mma_gemm_kernel<HH, 1>,
                         cudaFuncAttributeMaxDynamicSharedMemorySize, SMEM2);

    zero_kernel<<<(NN + 255) / 256, 256>>>();
    hist_kernel<<<(EE + 255) / 256, 256>>>(dst);
    degscan_kernel<<<NB, 1024>>>(NB);
    fill_kernel<<<(EE + 255) / 256, 256>>>(src, dst);

    // ---- layer 1 ----
    mma_gemm_kernel<INF, 0><<<(NN + 127) / 128, 256, SMEM1>>>(x, W1, hP, nullptr, nullptr);
    aggstats_kernel<<<AGG_BLOCKS, 256>>>(hP, b1, aggP, 0);

    // ---- layer 2: BN(layer1)+ReLU fused into A-tile load (prep fused in-block) ----
    mma_gemm_kernel<HH, 1><<<(NN + 127) / 128, 256, SMEM2>>>(aggP, W2, hP, g1, bt1);
    aggstats_kernel<<<AGG_BLOCKS, 256>>>(hP, b2, aggP, 1);
    bnapply_kernel<<<(NN * 16 + 255) / 256, 256>>>(aggP, g2, bt2, out);
}